// round 16
// baseline (speedup 1.0000x reference)
#include <cuda_runtime.h>

// Problem constants
#define NB     8
#define NH     16
#define NS     2048
#define DD     64
#define HI     256
#define NITN   4
#define CHUNK  512
#define MT     32
#define INV_SC (1.0f / 32768.0f)     // 1/(chunk*D)

typedef unsigned long long U64;

// Final adapted weights per (b,h): [128][ W1 pair-major 16384 | W2 pair-major 16384 ]
// W1[d][e] at (d>>1)*512 + e*2 + (d&1)
// W2[e][o] at (e>>1)*128 + o*2 + (e&1)   (+ DD*HI base)
__device__ float g_W[NB * NH * (DD * HI + HI * DD)];

// ---------------- packed f32x2 helpers --------------------------------------
__device__ __forceinline__ U64 ld64s(const float* p) {
    return *reinterpret_cast<const U64*>(p);
}
__device__ __forceinline__ void st64s(float* p, U64 v) {
    *reinterpret_cast<U64*>(p) = v;
}
__device__ __forceinline__ U64 pack2(float lo, float hi) {
    U64 r; asm("mov.b64 %0, {%1, %2};" : "=l"(r) : "f"(lo), "f"(hi)); return r;
}
__device__ __forceinline__ float2 unp2(U64 v) {
    float2 f; asm("mov.b64 {%0, %1}, %2;" : "=f"(f.x), "=f"(f.y) : "l"(v)); return f;
}
__device__ __forceinline__ U64 ffma2(U64 a, U64 b, U64 c) {
    U64 d; asm("fma.rn.f32x2 %0, %1, %2, %3;" : "=l"(d) : "l"(a), "l"(b), "l"(c));
    return d;
}

// ---------------- fast accurate tanh (MUFU.EX2 + MUFU.RCP, ~1e-7 rel) -------
__device__ __forceinline__ float fast_tanh(float u) {
    float e = __expf(2.0f * u);
    return 1.0f - __fdividef(2.0f, e + 1.0f);
}

// ---------------- gelu (tanh approximation, matches jax.nn.gelu) ------------
__device__ __forceinline__ float gelu_fwd_bwd(float x, float* dg) {
    const float c0 = 0.7978845608028654f;
    const float a0 = 0.044715f;
    float x2 = x * x;
    float u  = c0 * x * fmaf(a0, x2, 1.0f);
    float t  = fast_tanh(u);
    float du = c0 * fmaf(3.0f * a0, x2, 1.0f);
    *dg = 0.5f * (1.0f + t) + 0.5f * x * (1.0f - t * t) * du;
    return 0.5f * x * (1.0f + t);
}
__device__ __forceinline__ float gelu_f(float x) {
    const float c0 = 0.7978845608028654f;
    const float a0 = 0.044715f;
    float u = c0 * x * fmaf(a0, x * x, 1.0f);
    return 0.5f * x * (1.0f + fast_tanh(u));
}

// ---------------- training smem layout (floats) -----------------------------
// sW1p [32 d2][256 e][2]  @ 0      16384
// sW2  [256][66]          @ 16384  16896
// sGp  [32][256]          @ 33280   8192   (gelu', overwritten in-place with dZ)
// sH   [32][256]          @ 41472   8192
// sX2  [2][32][64]        @ 49664   4096   (double-buffered X)
// sE   [32][64]           @ 53760   2048
#define OFF_W1P 0
#define OFF_W2  16384
#define OFF_GP  33280
#define OFF_H   41472
#define OFF_X   49664
#define OFF_E   53760
#define TRAIN_SMEM_BYTES (55808 * 4)

__global__ __launch_bounds__(256, 1)
void ttt_train_kernel(const float* __restrict__ kk, const float* __restrict__ vv,
                      const float* __restrict__ W1g, const float* __restrict__ W2g) {
    extern __shared__ float sm[];
    float* sW1p = sm + OFF_W1P;
    float* sW2  = sm + OFF_W2;   // stride 66
    float* sGp  = sm + OFF_GP;
    float* sH   = sm + OFF_H;
    float* sX2  = sm + OFF_X;    // two 2048-float buffers
    float* sE   = sm + OFF_E;

    const int bh   = blockIdx.x;
    const int h    = bh & (NH - 1);
    const int tid  = threadIdx.x;
    const int lane = tid & 31;
    const int rg   = tid >> 5;          // warp 0..7
    // G1 mapping: 2 row-blocks of 16 x 4 e-quarters
    const int rb1  = rg & 1;            // row block (16 rows)
    const int q1   = rg >> 1;           // e quarter (64 cols)
    // G2 mapping
    const int o2   = tid & 63;          // output col
    const int mg   = (tid >> 6) * 8;    // row base (8 rows)
    // G4 mapping
    const int hr   = tid >> 7;          // row half (16 rows)
    const int c0   = tid & 127;         // dH column base

    const float* gW1 = W1g + (size_t)h * DD * HI;
    const float* gW2 = W2g + (size_t)h * HI * DD;
    for (int i = tid; i < DD * HI; i += 256) {
        int d = i >> 8, e = i & 255;
        sW1p[(d >> 1) * 512 + e * 2 + (d & 1)] = gW1[i];
    }
    for (int i = tid; i < HI * DD; i += 256) {
        int e = i >> 6, o = i & 63;
        sW2[e * 66 + o] = gW2[i];
    }

    const float* kb = kk + (size_t)bh * NS * DD;
    const float* vb = vv + (size_t)bh * NS * DD;

    // preload X tile 0 into buffer 0
    #pragma unroll
    for (int r = 0; r < 2; ++r) {
        int i4 = tid + 256 * r;
        *reinterpret_cast<float4*>(&sX2[i4 * 4]) =
            *reinterpret_cast<const float4*>(&kb[i4 * 4]);
    }
    __syncthreads();

    // Persistent gradient accumulators
    U64 dW1a[4][8];   // d-pair p = rg*4+pp ; e = lane+32*j -> {dW1[2p][e], dW1[2p+1][e]}
    U64 dW2a[16][2];  // e-pair pe: rows {rg*32+2pe, +1}; o = lane+32c

    for (int t = 0; t < 64; ++t) {      // flat tile index: rowbase = t*32
        const int rowbase = t * MT;
        float* sXc = sX2 + (t & 1) * 2048;
        float* sXn = sX2 + ((t + 1) & 1) * 2048;

        if ((t & 15) == 0) {
            #pragma unroll
            for (int pp = 0; pp < 4; ++pp)
                #pragma unroll
                for (int j = 0; j < 8; ++j) dW1a[pp][j] = 0ull;
            #pragma unroll
            for (int pe = 0; pe < 16; ++pe) { dW2a[pe][0] = 0ull; dW2a[pe][1] = 0ull; }
        }

        // prefetch Y for the G2 epilogue (rows mg+i, col o2)
        float yv[8];
        #pragma unroll
        for (int i = 0; i < 8; ++i)
            yv[i] = vb[(size_t)(rowbase + mg + i) * DD + o2];

        // ---- G1: Z = X @ W1 (K-pair over d), single pass.
        //      rows rb1*16..+16, cols {e0, e0+32}
        {
            const int e0 = q1 * 64 + lane;
            U64 acc[16][2];
            #pragma unroll
            for (int r = 0; r < 16; ++r) { acc[r][0] = 0ull; acc[r][1] = 0ull; }
            #pragma unroll 4
            for (int dc = 0; dc < 16; ++dc) {       // 4 d per iter
                U64 b00 = ld64s(&sW1p[(2 * dc) * 512 + e0 * 2]);
                U64 b01 = ld64s(&sW1p[(2 * dc + 1) * 512 + e0 * 2]);
                U64 b10 = ld64s(&sW1p[(2 * dc) * 512 + (e0 + 32) * 2]);
                U64 b11 = ld64s(&sW1p[(2 * dc + 1) * 512 + (e0 + 32) * 2]);
                #pragma unroll
                for (int r = 0; r < 16; ++r) {
                    ulonglong2 a = *reinterpret_cast<const ulonglong2*>(
                        &sXc[(rb1 * 16 + r) * 64 + 4 * dc]);
                    acc[r][0] = ffma2(a.x, b00, acc[r][0]);
                    acc[r][0] = ffma2(a.y, b01, acc[r][0]);
                    acc[r][1] = ffma2(a.x, b10, acc[r][1]);
                    acc[r][1] = ffma2(a.y, b11, acc[r][1]);
                }
            }
            #pragma unroll
            for (int r = 0; r < 16; ++r)
                #pragma unroll
                for (int c = 0; c < 2; ++c) {
                    float2 s = unp2(acc[r][c]);
                    float z = s.x + s.y, gp;
                    float hv = gelu_fwd_bwd(z, &gp);
                    int idx = (rb1 * 16 + r) * HI + e0 + 32 * c;
                    sH[idx]  = hv;
                    sGp[idx] = gp;
                }
        }
        __syncthreads();

        // ---- G2: E = (H @ W2 - Y) * INV_SC. rows mg+i, col o2, K-pairs over e
        {
            U64 eacc[8];
            #pragma unroll
            for (int i = 0; i < 8; ++i) eacc[i] = 0ull;
            #pragma unroll 2
            for (int ep2 = 0; ep2 < 64; ++ep2) {   // 4 e per iter
                float w0 = sW2[(4 * ep2 + 0) * 66 + o2];
                float w1 = sW2[(4 * ep2 + 1) * 66 + o2];
                float w2 = sW2[(4 * ep2 + 2) * 66 + o2];
                float w3 = sW2[(4 * ep2 + 3) * 66 + o2];
                U64 b0 = pack2(w0, w1), b1 = pack2(w2, w3);
                #pragma unroll
                for (int i = 0; i < 8; ++i) {
                    ulonglong2 a = *reinterpret_cast<const ulonglong2*>(
                        &sH[(mg + i) * HI + 4 * ep2]);
                    eacc[i] = ffma2(a.x, b0, eacc[i]);
                    eacc[i] = ffma2(a.y, b1, eacc[i]);
                }
            }
            #pragma unroll
            for (int i = 0; i < 8; ++i) {
                float2 s = unp2(eacc[i]);
                sE[(mg + i) * DD + o2] = (s.x + s.y - yv[i]) * INV_SC;
            }
        }
        __syncthreads();

        // ---- G3 + G4 merged phase, plus X(t+1) prefetch into the idle buffer
        //      (race-free: G3 reads sH/sE; G4 reads sE/sW2/sGp and writes only
        //       its OWN sGp elements; sXn is read by no one this phase)

        // X prefetch for next tile (clamped at the last tile; redundant re-read)
        {
            const int nt  = (t + 1 < 64) ? (t + 1) : 63;
            const int nrb = nt * MT;
            #pragma unroll
            for (int r = 0; r < 2; ++r) {
                int i4 = tid + 256 * r;
                *reinterpret_cast<float4*>(&sXn[i4 * 4]) =
                    *reinterpret_cast<const float4*>(&kb[(size_t)nrb * DD + i4 * 4]);
            }
        }

        // G3: dW2 += H^T @ E  (e-pairs rg*32+2pe, o = lane+32c)
        #pragma unroll 2
        for (int m = 0; m < MT; ++m) {
            float v0 = sE[m * DD + lane];
            float v1 = sE[m * DD + lane + 32];
            U64 b0 = pack2(v0, v0);
            U64 b1 = pack2(v1, v1);
            #pragma unroll
            for (int pe2 = 0; pe2 < 8; ++pe2) {    // 4 e per iter (2 pairs)
                ulonglong2 a = *reinterpret_cast<const ulonglong2*>(
                    &sH[m * HI + rg * 32 + 4 * pe2]);
                dW2a[2 * pe2][0]     = ffma2(a.x, b0, dW2a[2 * pe2][0]);
                dW2a[2 * pe2][1]     = ffma2(a.x, b1, dW2a[2 * pe2][1]);
                dW2a[2 * pe2 + 1][0] = ffma2(a.y, b0, dW2a[2 * pe2 + 1][0]);
                dW2a[2 * pe2 + 1][1] = ffma2(a.y, b1, dW2a[2 * pe2 + 1][1]);
            }
        }

        // G4: dH = E @ W2^T ; dZ = dH * gelu'  (written IN PLACE into sGp)
        //     rows hr*16..+16, cols {c0, c0+128}, K-pairs over o
        {
            U64 g4[16][2];
            #pragma unroll
            for (int m = 0; m < 16; ++m) { g4[m][0] = 0ull; g4[m][1] = 0ull; }
            #pragma unroll 2
            for (int op2 = 0; op2 < 16; ++op2) {   // 4 o per iter
                U64 b0a = ld64s(&sW2[c0 * 66 + 4 * op2]);
                U64 b0b = ld64s(&sW2[c0 * 66 + 4 * op2 + 2]);
                U64 b1a = ld64s(&sW2[(c0 + 128) * 66 + 4 * op2]);
                U64 b1b = ld64s(&sW2[(c0 + 128) * 66 + 4 * op2 + 2]);
                #pragma unroll
                for (int m = 0; m < 16; ++m) {
                    ulonglong2 a = *reinterpret_cast<const ulonglong2*>(
                        &sE[(hr * 16 + m) * DD + 4 * op2]);
                    g4[m][0] = ffma2(a.x, b0a, g4[m][0]);
                    g4[m][0] = ffma2(a.y, b0b, g4[m][0]);
                    g4[m][1] = ffma2(a.x, b1a, g4[m][1]);
                    g4[m][1] = ffma2(a.y, b1b, g4[m][1]);
                }
            }
            #pragma unroll
            for (int m = 0; m < 16; ++m) {
                float2 s0 = unp2(g4[m][0]);
                float2 s1 = unp2(g4[m][1]);
                int idx = (hr * 16 + m) * HI + c0;
                sGp[idx]       = (s0.x + s0.y) * sGp[idx];
                sGp[idx + 128] = (s1.x + s1.y) * sGp[idx + 128];
            }
        }
        __syncthreads();

        // ---- G5: dW1 += X^T @ dZ  (dZ lives in sGp; X from current buffer)
        #pragma unroll 2
        for (int m = 0; m < MT; ++m) {
            ulonglong2 x01 = *reinterpret_cast<const ulonglong2*>(&sXc[m * 64 + rg * 8]);
            ulonglong2 x23 = *reinterpret_cast<const ulonglong2*>(&sXc[m * 64 + rg * 8 + 4]);
            #pragma unroll
            for (int j = 0; j < 8; ++j) {
                float dz = sGp[m * HI + lane + 32 * j];
                U64 bz = pack2(dz, dz);
                dW1a[0][j] = ffma2(x01.x, bz, dW1a[0][j]);
                dW1a[1][j] = ffma2(x01.y, bz, dW1a[1][j]);
                dW1a[2][j] = ffma2(x23.x, bz, dW1a[2][j]);
                dW1a[3][j] = ffma2(x23.y, bz, dW1a[3][j]);
            }
        }
        __syncthreads();   // protect sH/sGp/sE before next tile (sXc free after G5)

        // ---- SGD update (lr = 1.0) at iteration boundaries
        if ((t & 15) == 15) {
            #pragma unroll
            for (int pp = 0; pp < 4; ++pp)
                #pragma unroll
                for (int j = 0; j < 8; ++j) {
                    int addr = (rg * 4 + pp) * 512 + (lane + 32 * j) * 2;
                    float2 w = unp2(ld64s(&sW1p[addr]));
                    float2 g = unp2(dW1a[pp][j]);
                    st64s(&sW1p[addr], pack2(w.x - g.x, w.y - g.y));
                }
            #pragma unroll
            for (int pe = 0; pe < 16; ++pe) {
                int e = rg * 32 + 2 * pe;
                #pragma unroll
                for (int c = 0; c < 2; ++c) {
                    float2 g = unp2(dW2a[pe][c]);
                    int o = lane + 32 * c;
                    sW2[e * 66 + o]       -= g.x;
                    sW2[(e + 1) * 66 + o] -= g.y;
                }
            }
            __syncthreads();
        }
    }

    // Store final adapted weights: W1 pair-major (d), W2 pair-major (e)
    float* gw = g_W + (size_t)bh * (DD * HI + HI * DD);
    for (int i = tid; i < DD * HI; i += 256) gw[i] = sW1p[i];
    for (int i = tid; i < HI * DD; i += 256) {
        int e = i >> 6, o = i & 63;
        gw[DD * HI + (e >> 1) * 128 + o * 2 + (e & 1)] = sW2[e * 66 + o];
    }
}

// ---------------- eval: e-chunked fused MLP, now 3 CTAs/SM ------------------
// smem (floats): sQ [64][64] @0 | sW1c [32 d2][64 e][2] @4096 |
//                sW2c [32 e2][64 o][2] @8192 | sHc [64][64] @12288
#define EOFF_Q   0
#define EOFF_W1C 4096
#define EOFF_W2C 8192
#define EOFF_HC  12288
#define EVAL_SMEM_BYTES (16384 * 4)

__global__ __launch_bounds__(256, 3)
void ttt_eval_kernel(const float* __restrict__ qq, float* __restrict__ out) {
    extern __shared__ float sm[];
    float* sQ   = sm + EOFF_Q;
    float* sW1c = sm + EOFF_W1C;
    float* sW2c = sm + EOFF_W2C;
    float* sHc  = sm + EOFF_HC;

    const int tile = blockIdx.x;     // 0..31
    const int bh   = blockIdx.y;     // 0..127
    const int b    = bh >> 4;
    const int h    = bh & 15;
    const int tid  = threadIdx.x;
    const int lane = tid & 31;
    const int rb   = tid >> 5;       // row block (8 rows)

    const float* gw  = g_W + (size_t)bh * (DD * HI + HI * DD);
    const float* gw2 = gw + DD * HI;
    const float* qb  = qq + ((size_t)bh * NS + tile * 64) * DD;

    // load Q tile (plain, float4)
    #pragma unroll
    for (int r = 0; r < 4; ++r) {
        int i4 = tid + 256 * r;
        *reinterpret_cast<float4*>(&sQ[i4 * 4]) =
            *reinterpret_cast<const float4*>(&qb[i4 * 4]);
    }

    U64 oacc[8][2];   // rows rb*8+i, cols {lane, lane+32}; K-pair over e
    #pragma unroll
    for (int i = 0; i < 8; ++i) { oacc[i][0] = 0ull; oacc[i][1] = 0ull; }

    for (int c = 0; c < 4; ++c) {
        __syncthreads();   // previous chunk consumers done (covers sQ fill too)
        // load W1 chunk: rows d2, 128 consecutive floats each
        #pragma unroll
        for (int r = 0; r < 4; ++r) {
            int i4 = tid + 256 * r;
            int d2 = i4 >> 5, off = (i4 & 31) * 4;
            *reinterpret_cast<float4*>(&sW1c[d2 * 128 + off]) =
                *reinterpret_cast<const float4*>(&gw[d2 * 512 + c * 128 + off]);
        }
        // load W2 chunk: contiguous 4096 floats
        #pragma unroll
        for (int r = 0; r < 4; ++r) {
            int i4 = tid + 256 * r;
            *reinterpret_cast<float4*>(&sW2c[i4 * 4]) =
                *reinterpret_cast<const float4*>(&gw2[c * 4096 + i4 * 4]);
        }
        __syncthreads();

        // Z chunk: rows rb*8..+8, e-cols {lane, lane+32}, K-pair over d
        {
            U64 zacc[8][2];
            #pragma unroll
            for (int i = 0; i < 8; ++i) { zacc[i][0] = 0ull; zacc[i][1] = 0ull; }
            #pragma unroll 4
            for (int dc = 0; dc < 16; ++dc) {    // 4 d per iter
                ulonglong2 aa[8];
                #pragma unroll
                for (int r = 0; r < 8; ++r)
                    aa[r] = *reinterpret_cast<const ulonglong2*>(
                        &sQ[(rb * 8 + r) * 64 + 4 * dc]);
                U64 b00 = ld64s(&sW1c[(2 * dc) * 128 + lane * 2]);
                U64 b01 = ld64s(&sW1c[(2 * dc + 1) * 128 + lane * 2]);
                U64 b10 = ld64s(&sW1c[(2 * dc) * 128 + (lane + 32) * 2]);
                U64 b11 = ld64s(&sW1c[(2 * dc + 1) * 128 + (lane + 32) * 2]);
                #pragma unroll
                for (int r = 0; r < 8; ++r) {
                    zacc[r][0] = ffma2(aa[r].x, b00, zacc[r][0]);
                    zacc[r][0] = ffma2(aa[r].y, b01, zacc[r][0]);
                    zacc[r][1] = ffma2(aa[r].x, b10, zacc[r][1]);
                    zacc[r][1] = ffma2(aa[r].y, b11, zacc[r][1]);
                }
            }
            #pragma unroll
            for (int r = 0; r < 8; ++r)
                #pragma unroll
                for (int g = 0; g < 2; ++g) {
                    float2 s = unp2(zacc[r][g]);
                    sHc[(rb * 8 + r) * 64 + lane + 32 * g] = gelu_f(s.x + s.y);
                }
        }
        __syncthreads();

        // O partial: rows rb*8..+8, cols {lane, lane+32}, K-pair over chunk e
        #pragma unroll 2
        for (int ec = 0; ec < 16; ++ec) {       // 4 e per iter (2 e-pairs)
            U64 b00 = ld64s(&sW2c[(2 * ec) * 128 + lane * 2]);
            U64 b01 = ld64s(&sW2c[(2 * ec + 1) * 128 + lane * 2]);
            U64 b10 = ld64s(&sW2c[(2 * ec) * 128 + (lane + 32) * 2]);
            U64 b11 = ld64s(&sW2c[(2 * ec + 1) * 128 + (lane + 32) * 2]);
            #pragma unroll
            for (int i = 0; i < 8; ++i) {
                ulonglong2 a = *reinterpret_cast<const ulonglong2*>(
                    &sHc[(rb * 8 + i) * 64 + 4 * ec]);
                oacc[i][0] = ffma2(a.x, b00, oacc[i][0]);
                oacc[i][0] = ffma2(a.y, b01, oacc[i][0]);
                oacc[i][1] = ffma2(a.x, b10, oacc[i][1]);
                oacc[i][1] = ffma2(a.y, b11, oacc[i][1]);
            }
        }
    }

    // write out[b, n, h*64 + o]
    #pragma unroll
    for (int i = 0; i < 8; ++i) {
        float2 s0 = unp2(oacc[i][0]);
        float2 s1 = unp2(oacc[i][1]);
        int n = tile * 64 + rb * 8 + i;
        size_t base = ((size_t)b * NS + n) * (NH * DD) + h * DD;
        out[base + lane]      = s0.x + s0.y;
        out[base + lane + 32] = s1.x + s1.y;
    }
}

extern "C" void kernel_launch(void* const* d_in, const int* in_sizes, int n_in,
                              void* d_out, int out_size) {
    const float* q  = (const float*)d_in[0];
    const float* k  = (const float*)d_in[1];
    const float* v  = (const float*)d_in[2];
    const float* W1 = (const float*)d_in[3];
    const float* W2 = (const float*)d_in[4];
    float* out = (float*)d_out;

    cudaFuncSetAttribute(ttt_train_kernel,
                         cudaFuncAttributeMaxDynamicSharedMemorySize, TRAIN_SMEM_BYTES);
    cudaFuncSetAttribute(ttt_eval_kernel,
                         cudaFuncAttributeMaxDynamicSharedMemorySize, EVAL_SMEM_BYTES);

    ttt_train_kernel<<<NB * NH, 256, TRAIN_SMEM_BYTES>>>(k, v, W1, W2);
    ttt_eval_kernel<<<dim3(NS / 64, NB * NH), 256, EVAL_SMEM_BYTES>>>(q, out);
}

// round 17
// speedup vs baseline: 1.0460x; 1.0460x over previous
#include <cuda_runtime.h>

// Problem constants
#define NB     8
#define NH     16
#define NS     2048
#define DD     64
#define HI     256
#define NITN   4
#define CHUNK  512
#define MT     32
#define NTILE  (CHUNK / MT)          // 16
#define INV_SC (1.0f / 32768.0f)     // 1/(chunk*D)

typedef unsigned long long U64;

// Final adapted weights per (b,h): [128][ W1 pair-major 16384 | W2 pair-major 16384 ]
// W1[d][e] at (d>>1)*512 + e*2 + (d&1)
// W2[e][o] at (e>>1)*128 + o*2 + (e&1)   (+ DD*HI base)
__device__ float g_W[NB * NH * (DD * HI + HI * DD)];

// ---------------- packed f32x2 helpers --------------------------------------
__device__ __forceinline__ U64 ld64s(const float* p) {
    return *reinterpret_cast<const U64*>(p);
}
__device__ __forceinline__ void st64s(float* p, U64 v) {
    *reinterpret_cast<U64*>(p) = v;
}
__device__ __forceinline__ U64 pack2(float lo, float hi) {
    U64 r; asm("mov.b64 %0, {%1, %2};" : "=l"(r) : "f"(lo), "f"(hi)); return r;
}
__device__ __forceinline__ float2 unp2(U64 v) {
    float2 f; asm("mov.b64 {%0, %1}, %2;" : "=f"(f.x), "=f"(f.y) : "l"(v)); return f;
}
__device__ __forceinline__ U64 ffma2(U64 a, U64 b, U64 c) {
    U64 d; asm("fma.rn.f32x2 %0, %1, %2, %3;" : "=l"(d) : "l"(a), "l"(b), "l"(c));
    return d;
}

// ---------------- fast accurate tanh (MUFU.EX2 + MUFU.RCP, ~1e-7 rel) -------
__device__ __forceinline__ float fast_tanh(float u) {
    float e = __expf(2.0f * u);
    return 1.0f - __fdividef(2.0f, e + 1.0f);
}

// ---------------- gelu (tanh approximation, matches jax.nn.gelu) ------------
__device__ __forceinline__ float gelu_fwd_bwd(float x, float* dg) {
    const float c0 = 0.7978845608028654f;
    const float a0 = 0.044715f;
    float x2 = x * x;
    float u  = c0 * x * fmaf(a0, x2, 1.0f);
    float t  = fast_tanh(u);
    float du = c0 * fmaf(3.0f * a0, x2, 1.0f);
    *dg = 0.5f * (1.0f + t) + 0.5f * x * (1.0f - t * t) * du;
    return 0.5f * x * (1.0f + t);
}
__device__ __forceinline__ float gelu_f(float x) {
    const float c0 = 0.7978845608028654f;
    const float a0 = 0.044715f;
    float u = c0 * x * fmaf(a0, x * x, 1.0f);
    return 0.5f * x * (1.0f + fast_tanh(u));
}

// ---------------- training smem layout (floats) -----------------------------
// sW1p [32 d2][256 e][2]  @ 0      16384
// sW2  [256][66]          @ 16384  16896
// sGp  [32][256]          @ 33280   8192   (gelu', overwritten in-place with dZ)
// sH   [32][256]          @ 41472   8192
// sX   [32][64]           @ 49664   2048
// sE   [32][64]           @ 51712   2048
#define OFF_W1P 0
#define OFF_W2  16384
#define OFF_GP  33280
#define OFF_H   41472
#define OFF_X   49664
#define OFF_E   51712
#define TRAIN_SMEM_BYTES (53760 * 4)

__global__ __launch_bounds__(256, 1)
void ttt_train_kernel(const float* __restrict__ kk, const float* __restrict__ vv,
                      const float* __restrict__ W1g, const float* __restrict__ W2g) {
    extern __shared__ float sm[];
    float* sW1p = sm + OFF_W1P;
    float* sW2  = sm + OFF_W2;   // stride 66
    float* sGp  = sm + OFF_GP;
    float* sH   = sm + OFF_H;
    float* sX   = sm + OFF_X;
    float* sE   = sm + OFF_E;

    const int bh   = blockIdx.x;
    const int h    = bh & (NH - 1);
    const int tid  = threadIdx.x;
    const int lane = tid & 31;
    const int rg   = tid >> 5;          // warp 0..7
    // G1 mapping: 2 row-blocks of 16 x 4 e-quarters
    const int rb1  = rg & 1;            // row block (16 rows)
    const int q1   = rg >> 1;           // e quarter (64 cols)
    // G2 mapping
    const int o2   = tid & 63;          // output col
    const int mg   = (tid >> 6) * 8;    // row base (8 rows)
    // G4 mapping
    const int hr   = tid >> 7;          // row half (16 rows)
    const int c0   = tid & 127;         // dH column base

    const float* gW1 = W1g + (size_t)h * DD * HI;
    const float* gW2 = W2g + (size_t)h * HI * DD;
    for (int i = tid; i < DD * HI; i += 256) {
        int d = i >> 8, e = i & 255;
        sW1p[(d >> 1) * 512 + e * 2 + (d & 1)] = gW1[i];
    }
    for (int i = tid; i < HI * DD; i += 256) {
        int e = i >> 6, o = i & 63;
        sW2[e * 66 + o] = gW2[i];
    }
    __syncthreads();

    const float* kb = kk + (size_t)bh * NS * DD;
    const float* vb = vv + (size_t)bh * NS * DD;

    // Persistent gradient accumulators
    U64 dW1a[4][8];   // d-pair p = rg*4+pp ; e = lane+32*j -> {dW1[2p][e], dW1[2p+1][e]}
    U64 dW2a[16][2];  // e-pair pe: rows {rg*32+2pe, +1}; o = lane+32c

    for (int it = 0; it < NITN; ++it) {
        #pragma unroll
        for (int pp = 0; pp < 4; ++pp)
            #pragma unroll
            for (int j = 0; j < 8; ++j) dW1a[pp][j] = 0ull;
        #pragma unroll
        for (int pe = 0; pe < 16; ++pe) { dW2a[pe][0] = 0ull; dW2a[pe][1] = 0ull; }

        for (int mt = 0; mt < NTILE; ++mt) {
            const int rowbase = it * CHUNK + mt * MT;

            // prefetch Y for the G2 epilogue (rows mg+i, col o2)
            float yv[8];
            #pragma unroll
            for (int i = 0; i < 8; ++i)
                yv[i] = vb[(size_t)(rowbase + mg + i) * DD + o2];

            // load X tile (plain layout, float4)
            #pragma unroll
            for (int r = 0; r < 2; ++r) {
                int i4 = tid + 256 * r;
                *reinterpret_cast<float4*>(&sX[i4 * 4]) =
                    *reinterpret_cast<const float4*>(&kb[(size_t)rowbase * DD + i4 * 4]);
            }
            __syncthreads();

            // ---- G1: Z = X @ W1 (K-pair over d), single pass.
            //      rows rb1*16..+16, cols {e0, e0+32}
            {
                const int e0 = q1 * 64 + lane;
                U64 acc[16][2];
                #pragma unroll
                for (int r = 0; r < 16; ++r) { acc[r][0] = 0ull; acc[r][1] = 0ull; }
                #pragma unroll 4
                for (int dc = 0; dc < 16; ++dc) {       // 4 d per iter
                    U64 b00 = ld64s(&sW1p[(2 * dc) * 512 + e0 * 2]);
                    U64 b01 = ld64s(&sW1p[(2 * dc + 1) * 512 + e0 * 2]);
                    U64 b10 = ld64s(&sW1p[(2 * dc) * 512 + (e0 + 32) * 2]);
                    U64 b11 = ld64s(&sW1p[(2 * dc + 1) * 512 + (e0 + 32) * 2]);
                    #pragma unroll
                    for (int r = 0; r < 16; ++r) {
                        ulonglong2 a = *reinterpret_cast<const ulonglong2*>(
                            &sX[(rb1 * 16 + r) * 64 + 4 * dc]);
                        acc[r][0] = ffma2(a.x, b00, acc[r][0]);
                        acc[r][0] = ffma2(a.y, b01, acc[r][0]);
                        acc[r][1] = ffma2(a.x, b10, acc[r][1]);
                        acc[r][1] = ffma2(a.y, b11, acc[r][1]);
                    }
                }
                #pragma unroll
                for (int r = 0; r < 16; ++r)
                    #pragma unroll
                    for (int c = 0; c < 2; ++c) {
                        float2 s = unp2(acc[r][c]);
                        float z = s.x + s.y, gp;
                        float hv = gelu_fwd_bwd(z, &gp);
                        int idx = (rb1 * 16 + r) * HI + e0 + 32 * c;
                        sH[idx]  = hv;
                        sGp[idx] = gp;
                    }
            }
            __syncthreads();

            // ---- G2: E = (H @ W2 - Y) * INV_SC. rows mg+i, col o2, K-pairs over e
            {
                U64 eacc[8];
                #pragma unroll
                for (int i = 0; i < 8; ++i) eacc[i] = 0ull;
                #pragma unroll 2
                for (int ep2 = 0; ep2 < 64; ++ep2) {   // 4 e per iter
                    float w0 = sW2[(4 * ep2 + 0) * 66 + o2];
                    float w1 = sW2[(4 * ep2 + 1) * 66 + o2];
                    float w2 = sW2[(4 * ep2 + 2) * 66 + o2];
                    float w3 = sW2[(4 * ep2 + 3) * 66 + o2];
                    U64 b0 = pack2(w0, w1), b1 = pack2(w2, w3);
                    #pragma unroll
                    for (int i = 0; i < 8; ++i) {
                        ulonglong2 a = *reinterpret_cast<const ulonglong2*>(
                            &sH[(mg + i) * HI + 4 * ep2]);
                        eacc[i] = ffma2(a.x, b0, eacc[i]);
                        eacc[i] = ffma2(a.y, b1, eacc[i]);
                    }
                }
                #pragma unroll
                for (int i = 0; i < 8; ++i) {
                    float2 s = unp2(eacc[i]);
                    sE[(mg + i) * DD + o2] = (s.x + s.y - yv[i]) * INV_SC;
                }
            }
            __syncthreads();

            // ---- G3 + G4 merged phase (race-free: G3 reads sH/sE; G4 reads
            //      sE/sW2/sGp and writes only its OWN sGp elements in place)

            // G3: dW2 += H^T @ E  (e-pairs rg*32+2pe, o = lane+32c)
            #pragma unroll 2
            for (int m = 0; m < MT; ++m) {
                float v0 = sE[m * DD + lane];
                float v1 = sE[m * DD + lane + 32];
                U64 b0 = pack2(v0, v0);
                U64 b1 = pack2(v1, v1);
                #pragma unroll
                for (int pe2 = 0; pe2 < 8; ++pe2) {    // 4 e per iter (2 pairs)
                    ulonglong2 a = *reinterpret_cast<const ulonglong2*>(
                        &sH[m * HI + rg * 32 + 4 * pe2]);
                    dW2a[2 * pe2][0]     = ffma2(a.x, b0, dW2a[2 * pe2][0]);
                    dW2a[2 * pe2][1]     = ffma2(a.x, b1, dW2a[2 * pe2][1]);
                    dW2a[2 * pe2 + 1][0] = ffma2(a.y, b0, dW2a[2 * pe2 + 1][0]);
                    dW2a[2 * pe2 + 1][1] = ffma2(a.y, b1, dW2a[2 * pe2 + 1][1]);
                }
            }

            // G4: dH = E @ W2^T ; dZ = dH * gelu'  (written IN PLACE into sGp)
            //     rows hr*16..+16, cols {c0, c0+128}, K-pairs over o
            {
                U64 g4[16][2];
                #pragma unroll
                for (int m = 0; m < 16; ++m) { g4[m][0] = 0ull; g4[m][1] = 0ull; }
                #pragma unroll 2
                for (int op2 = 0; op2 < 16; ++op2) {   // 4 o per iter
                    U64 b0a = ld64s(&sW2[c0 * 66 + 4 * op2]);
                    U64 b0b = ld64s(&sW2[c0 * 66 + 4 * op2 + 2]);
                    U64 b1a = ld64s(&sW2[(c0 + 128) * 66 + 4 * op2]);
                    U64 b1b = ld64s(&sW2[(c0 + 128) * 66 + 4 * op2 + 2]);
                    #pragma unroll
                    for (int m = 0; m < 16; ++m) {
                        ulonglong2 a = *reinterpret_cast<const ulonglong2*>(
                            &sE[(hr * 16 + m) * DD + 4 * op2]);
                        g4[m][0] = ffma2(a.x, b0a, g4[m][0]);
                        g4[m][0] = ffma2(a.y, b0b, g4[m][0]);
                        g4[m][1] = ffma2(a.x, b1a, g4[m][1]);
                        g4[m][1] = ffma2(a.y, b1b, g4[m][1]);
                    }
                }
                #pragma unroll
                for (int m = 0; m < 16; ++m) {
                    float2 s0 = unp2(g4[m][0]);
                    float2 s1 = unp2(g4[m][1]);
                    int idx = (hr * 16 + m) * HI + c0;
                    sGp[idx]       = (s0.x + s0.y) * sGp[idx];
                    sGp[idx + 128] = (s1.x + s1.y) * sGp[idx + 128];
                }
            }
            __syncthreads();

            // ---- G5: dW1 += X^T @ dZ  (dZ lives in sGp)
            #pragma unroll 2
            for (int m = 0; m < MT; ++m) {
                ulonglong2 x01 = *reinterpret_cast<const ulonglong2*>(&sX[m * 64 + rg * 8]);
                ulonglong2 x23 = *reinterpret_cast<const ulonglong2*>(&sX[m * 64 + rg * 8 + 4]);
                #pragma unroll
                for (int j = 0; j < 8; ++j) {
                    float dz = sGp[m * HI + lane + 32 * j];
                    U64 bz = pack2(dz, dz);
                    dW1a[0][j] = ffma2(x01.x, bz, dW1a[0][j]);
                    dW1a[1][j] = ffma2(x01.y, bz, dW1a[1][j]);
                    dW1a[2][j] = ffma2(x23.x, bz, dW1a[2][j]);
                    dW1a[3][j] = ffma2(x23.y, bz, dW1a[3][j]);
                }
            }
            __syncthreads();   // protect sX/sH/sGp/sE before next tile
        }

        // ---- SGD update (lr = 1.0); W1 pair-major
        #pragma unroll
        for (int pp = 0; pp < 4; ++pp)
            #pragma unroll
            for (int j = 0; j < 8; ++j) {
                int addr = (rg * 4 + pp) * 512 + (lane + 32 * j) * 2;
                float2 w = unp2(ld64s(&sW1p[addr]));
                float2 g = unp2(dW1a[pp][j]);
                st64s(&sW1p[addr], pack2(w.x - g.x, w.y - g.y));
            }
        #pragma unroll
        for (int pe = 0; pe < 16; ++pe) {
            int e = rg * 32 + 2 * pe;
            #pragma unroll
            for (int c = 0; c < 2; ++c) {
                float2 g = unp2(dW2a[pe][c]);
                int o = lane + 32 * c;
                sW2[e * 66 + o]       -= g.x;
                sW2[(e + 1) * 66 + o] -= g.y;
            }
        }
        __syncthreads();
    }

    // Store final adapted weights: W1 pair-major (d), W2 pair-major (e)
    float* gw = g_W + (size_t)bh * (DD * HI + HI * DD);
    for (int i = tid; i < DD * HI; i += 256) gw[i] = sW1p[i];
    for (int i = tid; i < HI * DD; i += 256) {
        int e = i >> 6, o = i & 63;
        gw[DD * HI + (e >> 1) * 128 + o * 2 + (e & 1)] = sW2[e * 66 + o];
    }
}

// ---------------- eval: e-chunked fused MLP, occ 2 --------------------------
// Z phase: rows rg*8..+8, two col passes (e = 32p+lane), zacc 8 U64.
// O phase: k-split R16xC2 — warp (rbO = rg&3, kh = rg>>2) accumulates rows
// rbO*16..+16 over its 32-e half of each chunk; halves combined via smem at end.
// smem (floats): sQ [64][64] @0 | sW1c [32 d2][64 e][2] @4096 |
//                sW2c [32 e2][64 o][2] @8192 | sHc [64][64] @12288
#define EOFF_Q   0
#define EOFF_W1C 4096
#define EOFF_W2C 8192
#define EOFF_HC  12288
#define EVAL_SMEM_BYTES (16384 * 4)

__global__ __launch_bounds__(256, 2)
void ttt_eval_kernel(const float* __restrict__ qq, float* __restrict__ out) {
    extern __shared__ float sm[];
    float* sQ   = sm + EOFF_Q;
    float* sW1c = sm + EOFF_W1C;
    float* sW2c = sm + EOFF_W2C;
    float* sHc  = sm + EOFF_HC;

    const int tile = blockIdx.x;     // 0..31
    const int bh   = blockIdx.y;     // 0..127
    const int b    = bh >> 4;
    const int h    = bh & 15;
    const int tid  = threadIdx.x;
    const int lane = tid & 31;
    const int rg   = tid >> 5;       // warp 0..7
    const int rbO  = rg & 3;         // O row block (16 rows)
    const int kh   = rg >> 2;        // O e-half (0/1)

    const float* gw  = g_W + (size_t)bh * (DD * HI + HI * DD);
    const float* gw2 = gw + DD * HI;
    const float* qb  = qq + ((size_t)bh * NS + tile * 64) * DD;

    // load Q tile (plain, float4)
    #pragma unroll
    for (int r = 0; r < 4; ++r) {
        int i4 = tid + 256 * r;
        *reinterpret_cast<float4*>(&sQ[i4 * 4]) =
            *reinterpret_cast<const float4*>(&qb[i4 * 4]);
    }

    // O accumulator: rows rbO*16+m, cols {lane, lane+32}; partial over kh e-half
    U64 oacc[16][2];
    #pragma unroll
    for (int m = 0; m < 16; ++m) { oacc[m][0] = 0ull; oacc[m][1] = 0ull; }

    for (int c = 0; c < 4; ++c) {
        __syncthreads();   // previous chunk consumers done (covers sQ fill too)
        // load W1 chunk: rows d2, 128 consecutive floats each
        #pragma unroll
        for (int r = 0; r < 4; ++r) {
            int i4 = tid + 256 * r;
            int d2 = i4 >> 5, off = (i4 & 31) * 4;
            *reinterpret_cast<float4*>(&sW1c[d2 * 128 + off]) =
                *reinterpret_cast<const float4*>(&gw[d2 * 512 + c * 128 + off]);
        }
        // load W2 chunk: contiguous 4096 floats
        #pragma unroll
        for (int r = 0; r < 4; ++r) {
            int i4 = tid + 256 * r;
            *reinterpret_cast<float4*>(&sW2c[i4 * 4]) =
                *reinterpret_cast<const float4*>(&gw2[c * 4096 + i4 * 4]);
        }
        __syncthreads();

        // Z chunk: rows rg*8..+8, two col passes (e = 32p+lane), K-pair over d
        #pragma unroll
        for (int p = 0; p < 2; ++p) {
            const int ec = 32 * p + lane;
            U64 zacc[8];
            #pragma unroll
            for (int r = 0; r < 8; ++r) zacc[r] = 0ull;
            #pragma unroll 4
            for (int dc = 0; dc < 16; ++dc) {    // 4 d per iter
                U64 b0 = ld64s(&sW1c[(2 * dc) * 128 + ec * 2]);
                U64 b1 = ld64s(&sW1c[(2 * dc + 1) * 128 + ec * 2]);
                #pragma unroll
                for (int r = 0; r < 8; ++r) {
                    ulonglong2 a = *reinterpret_cast<const ulonglong2*>(
                        &sQ[(rg * 8 + r) * 64 + 4 * dc]);
                    zacc[r] = ffma2(a.x, b0, zacc[r]);
                    zacc[r] = ffma2(a.y, b1, zacc[r]);
                }
            }
            #pragma unroll
            for (int r = 0; r < 8; ++r) {
                float2 s = unp2(zacc[r]);
                sHc[(rg * 8 + r) * 64 + ec] = gelu_f(s.x + s.y);
            }
        }
        __syncthreads();

        // O partial: rows rbO*16..+16, cols {lane, lane+32}, K over e-half kh
        #pragma unroll 2
        for (int ecc = 0; ecc < 8; ++ecc) {       // 4 e per iter within half
            const int e4 = kh * 32 + 4 * ecc;
            const int e2 = e4 >> 1;
            U64 b00 = ld64s(&sW2c[e2 * 128 + lane * 2]);
            U64 b01 = ld64s(&sW2c[(e2 + 1) * 128 + lane * 2]);
            U64 b10 = ld64s(&sW2c[e2 * 128 + (lane + 32) * 2]);
            U64 b11 = ld64s(&sW2c[(e2 + 1) * 128 + (lane + 32) * 2]);
            #pragma unroll
            for (int m = 0; m < 16; ++m) {
                ulonglong2 a = *reinterpret_cast<const ulonglong2*>(
                    &sHc[(rbO * 16 + m) * 64 + e4]);
                oacc[m][0] = ffma2(a.x, b00, oacc[m][0]);
                oacc[m][0] = ffma2(a.y, b01, oacc[m][0]);
                oacc[m][1] = ffma2(a.x, b10, oacc[m][1]);
                oacc[m][1] = ffma2(a.y, b11, oacc[m][1]);
            }
        }
    }

    // Combine kh halves: kh=1 writes partials to smem, kh=0 adds and stores.
    __syncthreads();   // last chunk's O reads of sHc done
    if (kh == 1) {
        #pragma unroll
        for (int m = 0; m < 16; ++m) {
            float2 s0 = unp2(oacc[m][0]);
            float2 s1 = unp2(oacc[m][1]);
            sHc[(rbO * 16 + m) * 64 + lane]      = s0.x + s0.y;
            sHc[(rbO * 16 + m) * 64 + lane + 32] = s1.x + s1.y;
        }
    }
    __syncthreads();
    if (kh == 0) {
        #pragma unroll
        for (int m = 0; m < 16; ++m) {
            float2 s0 = unp2(oacc[m][0]);
            float2 s1 = unp2(oacc[m][1]);
            int n = tile * 64 + rbO * 16 + m;
            size_t base = ((size_t)b * NS + n) * (NH * DD) + h * DD;
            out[base + lane]      = s0.x + s0.y + sHc[(rbO * 16 + m) * 64 + lane];
            out[base + lane + 32] = s1.x + s1.y + sHc[(rbO * 16 + m) * 64 + lane + 32];
        }
    }
}

extern "C" void kernel_launch(void* const* d_in, const int* in_sizes, int n_in,
                              void* d_out, int out_size) {
    const float* q  = (const float*)d_in[0];
    const float* k  = (const float*)d_in[1];
    const float* v  = (const float*)d_in[2];
    const float* W1 = (const float*)d_in[3];
    const float* W2 = (const float*)d_in[4];
    float* out = (float*)d_out;

    cudaFuncSetAttribute(ttt_train_kernel,
                         cudaFuncAttributeMaxDynamicSharedMemorySize, TRAIN_SMEM_BYTES);
    cudaFuncSetAttribute(ttt_eval_kernel,
                         cudaFuncAttributeMaxDynamicSharedMemorySize, EVAL_SMEM_BYTES);

    ttt_train_kernel<<<NB * NH, 256, TRAIN_SMEM_BYTES>>>(k, v, W1, W2);
    ttt_eval_kernel<<<dim3(NS / 64, NB * NH), 256, EVAL_SMEM_BYTES>>>(q, out);
}